// round 6
// baseline (speedup 1.0000x reference)
#include <cuda_runtime.h>
#include <cuda_bf16.h>
#include <cstdint>

// out[b,k] = log( sum_n exp(x[b,n]) * exp(acc[n,k]) ) - log( sum_n exp(acc[n,k]) )
// per (s,d) batch: GEMM M=128 (batch), N=512 (sums), K=512 (nodes_in)
// Pass 1: exp(X) -> bf16 scratch (removes 8x redundant exp, halves X traffic).
// Pass 2: bf16 HMMA GEMM; A via cp.async from scratch, B exp'd in-register.

#define NSD     256     // S*D
#define BDIM    128
#define NIN     512
#define NSUM    512
#define KC      32      // K chunk per iteration
#define NT      64      // N tile per CTA
#define APITCH  40      // bf16/row: 80B stride -> LDSM conflict-free
#define BPITCH  72      // bf16/row: 144B stride -> LDSM conflict-free
#define NCH     (NIN/KC)   // 16

// pre-exp'd X, bf16: [NSD][BDIM][NIN] = 16.8M elems = 33.5MB
__device__ __nv_bfloat16 g_xe[(size_t)NSD * BDIM * NIN];

__device__ __forceinline__ unsigned packbf(float a, float b) {
    __nv_bfloat162 h = __floats2bfloat162_rn(a, b);
    return *reinterpret_cast<unsigned const*>(&h);
}

__device__ __forceinline__ uint32_t s2u(const void* p) {
    uint32_t a;
    asm("{ .reg .u64 t; cvta.to.shared.u64 t, %1; cvt.u32.u64 %0, t; }" : "=r"(a) : "l"(p));
    return a;
}

// ---------------- Pass 1: Xe = bf16(exp(X)) ----------------
__global__ __launch_bounds__(256) void expx_kernel(const float* __restrict__ X) {
    const size_t i = ((size_t)blockIdx.x * blockDim.x + threadIdx.x) * 8;
    float4 a = *reinterpret_cast<const float4*>(X + i);
    float4 b = *reinterpret_cast<const float4*>(X + i + 4);
    uint4 u;
    u.x = packbf(__expf(a.x), __expf(a.y));
    u.y = packbf(__expf(a.z), __expf(a.w));
    u.z = packbf(__expf(b.x), __expf(b.y));
    u.w = packbf(__expf(b.z), __expf(b.w));
    *reinterpret_cast<uint4*>(g_xe + i) = u;
}

// ---------------- Pass 2: GEMM + log epilogue ----------------
__global__ __launch_bounds__(256, 2) void densesum_kernel(
    const float* __restrict__ W,   // [NSD][NIN][NSUM]
    float* __restrict__ O)         // [NSD][BDIM][NSUM]
{
    const int ct = blockIdx.x;     // N tile index, 0..7
    const int sd = blockIdx.y;     // 0..255

    const __nv_bfloat16* Xe = g_xe + (size_t)sd * BDIM * NIN;
    const float* Wp = W + (size_t)sd * NIN * NSUM + ct * NT;
    float*       Op = O + (size_t)sd * BDIM * NSUM + ct * NT;

    __shared__ __align__(16) __nv_bfloat16 As[2][BDIM * APITCH];
    __shared__ __align__(16) __nv_bfloat16 Bs[2][KC * BPITCH];
    __shared__ float csums[NT];

    const int t = threadIdx.x;
    if (t < NT) csums[t] = 0.f;

    const int warp = t >> 5, lane = t & 31;
    const int wm = warp >> 1;      // 0..3  (M position, 32 rows each)
    const int wn = warp & 1;       // 0..1  (N position, 32 cols each)
    const int l15 = lane & 15;
    const int lhi = lane >> 4;     // 0/1

    // B gmem load mapping
    const int br = t >> 4;
    const int bc = (t & 15) * 4;

    // A cp.async mapping: 512 chunks of 16B; thread handles cid = t, t+256
    // row = cid>>2 (0..127), c4 = cid&3  (4 x 16B per 64B row)
    const uint32_t As0 = s2u(&As[0][0]);
    const int arow0 = t >> 2,         ac40 = t & 3;
    const int arow1 = (t + 256) >> 2, ac41 = (t + 256) & 3;

    // ldmatrix per-lane base byte offsets (within a buffer)
    const uint32_t Bs0 = s2u(&Bs[0][0]);
    const uint32_t aln = (uint32_t)((wm * 32 + l15) * APITCH + lhi * 8) * 2;
    const uint32_t bln = (uint32_t)(l15 * BPITCH + wn * 32 + lhi * 8) * 2;

    float acc[2][4][4];
    #pragma unroll
    for (int i = 0; i < 2; i++)
        #pragma unroll
        for (int j = 0; j < 4; j++)
            #pragma unroll
            for (int k = 0; k < 4; k++) acc[i][j][k] = 0.f;

    float csum[4] = {0.f, 0.f, 0.f, 0.f};

    // prologue: A(0) -> buf0 via cp.async; B(0) -> regs
    {
        const uint32_t d0 = As0 + (uint32_t)(arow0 * 80 + ac40 * 16);
        const uint32_t d1 = As0 + (uint32_t)(arow1 * 80 + ac41 * 16);
        const __nv_bfloat16* s0 = Xe + (size_t)arow0 * NIN + ac40 * 8;
        const __nv_bfloat16* s1 = Xe + (size_t)arow1 * NIN + ac41 * 8;
        asm volatile("cp.async.cg.shared.global [%0], [%1], 16;" :: "r"(d0), "l"(s0));
        asm volatile("cp.async.cg.shared.global [%0], [%1], 16;" :: "r"(d1), "l"(s1));
        asm volatile("cp.async.commit_group;" ::: "memory");
    }
    float4 pb[2];
    #pragma unroll
    for (int j = 0; j < 2; j++)
        pb[j] = *reinterpret_cast<const float4*>(Wp + (size_t)(br + 16 * j) * NSUM + bc);

    for (int ch = 0; ch < NCH; ch++) {
        const int buf = ch & 1;

        // B: exp + bf16 + STS, plus column-sum accumulation
        #pragma unroll
        for (int j = 0; j < 2; j++) {
            float4 v = pb[j];
            float e0 = __expf(v.x), e1 = __expf(v.y), e2 = __expf(v.z), e3 = __expf(v.w);
            csum[0] += e0; csum[1] += e1; csum[2] += e2; csum[3] += e3;
            uint2 u = make_uint2(packbf(e0, e1), packbf(e2, e3));
            *reinterpret_cast<uint2*>(&Bs[buf][(br + 16 * j) * BPITCH + bc]) = u;
        }

        // A(ch) complete, then barrier (also retires all reads of buf^1)
        asm volatile("cp.async.wait_group 0;" ::: "memory");
        __syncthreads();

        // issue A(ch+1) -> buf^1; prefetch B(ch+1) regs
        if (ch + 1 < NCH) {
            const uint32_t abuf1 = As0 + (uint32_t)((buf ^ 1) * BDIM * APITCH * 2);
            const __nv_bfloat16* Xn = Xe + (ch + 1) * KC;
            const uint32_t d0 = abuf1 + (uint32_t)(arow0 * 80 + ac40 * 16);
            const uint32_t d1 = abuf1 + (uint32_t)(arow1 * 80 + ac41 * 16);
            const __nv_bfloat16* s0 = Xn + (size_t)arow0 * NIN + ac40 * 8;
            const __nv_bfloat16* s1 = Xn + (size_t)arow1 * NIN + ac41 * 8;
            asm volatile("cp.async.cg.shared.global [%0], [%1], 16;" :: "r"(d0), "l"(s0));
            asm volatile("cp.async.cg.shared.global [%0], [%1], 16;" :: "r"(d1), "l"(s1));
            asm volatile("cp.async.commit_group;" ::: "memory");

            const float* Wn = Wp + (size_t)(ch + 1) * KC * NSUM;
            #pragma unroll
            for (int j = 0; j < 2; j++)
                pb[j] = *reinterpret_cast<const float4*>(Wn + (size_t)(br + 16 * j) * NSUM + bc);
        }

        // MMA over this chunk (two k16 steps), fragments via ldmatrix
        const uint32_t abase = As0 + (uint32_t)(buf * BDIM * APITCH * 2);
        const uint32_t bbase = Bs0 + (uint32_t)(buf * KC * BPITCH * 2);
        #pragma unroll
        for (int ks = 0; ks < 2; ks++) {
            unsigned afr[2][4];
            #pragma unroll
            for (int mf = 0; mf < 2; mf++) {
                const uint32_t addr = abase + aln
                    + (uint32_t)(mf * 16 * APITCH * 2) + (uint32_t)(ks * 32);
                asm volatile(
                    "ldmatrix.sync.aligned.m8n8.x4.shared.b16 {%0,%1,%2,%3}, [%4];"
                    : "=r"(afr[mf][0]), "=r"(afr[mf][1]),
                      "=r"(afr[mf][2]), "=r"(afr[mf][3])
                    : "r"(addr));
            }
            unsigned bfr[2][4];
            #pragma unroll
            for (int np = 0; np < 2; np++) {
                const uint32_t addr = bbase + bln
                    + (uint32_t)(ks * 16 * BPITCH * 2) + (uint32_t)(np * 32);
                asm volatile(
                    "ldmatrix.sync.aligned.m8n8.x4.trans.shared.b16 {%0,%1,%2,%3}, [%4];"
                    : "=r"(bfr[np][0]), "=r"(bfr[np][1]),
                      "=r"(bfr[np][2]), "=r"(bfr[np][3])
                    : "r"(addr));
            }
            #pragma unroll
            for (int mf = 0; mf < 2; mf++)
                #pragma unroll
                for (int nf = 0; nf < 4; nf++) {
                    const int np = nf >> 1, sel = (nf & 1) * 2;
                    asm volatile(
                        "mma.sync.aligned.m16n8k16.row.col.f32.bf16.bf16.f32 "
                        "{%0,%1,%2,%3}, {%4,%5,%6,%7}, {%8,%9}, {%0,%1,%2,%3};\n"
                        : "+f"(acc[mf][nf][0]), "+f"(acc[mf][nf][1]),
                          "+f"(acc[mf][nf][2]), "+f"(acc[mf][nf][3])
                        : "r"(afr[mf][0]), "r"(afr[mf][1]),
                          "r"(afr[mf][2]), "r"(afr[mf][3]),
                          "r"(bfr[np][sel]), "r"(bfr[np][sel + 1]));
                }
        }
    }

    // reduce per-thread column sums (threads sharing bc cover disjoint n rows)
    atomicAdd(&csums[bc + 0], csum[0]);
    atomicAdd(&csums[bc + 1], csum[1]);
    atomicAdd(&csums[bc + 2], csum[2]);
    atomicAdd(&csums[bc + 3], csum[3]);
    __syncthreads();

    // epilogue: out = log(P) - log(C[col])
    const int g = lane >> 2, q = lane & 3;
    #pragma unroll
    for (int nf = 0; nf < 4; nf++) {
        const int c = wn * 32 + nf * 8 + q * 2;
        const float lc0 = __logf(csums[c]);
        const float lc1 = __logf(csums[c + 1]);
        #pragma unroll
        for (int mf = 0; mf < 2; mf++) {
            const int r0 = wm * 32 + mf * 16 + g;
            Op[(size_t)r0 * NSUM + c]           = __logf(acc[mf][nf][0]) - lc0;
            Op[(size_t)r0 * NSUM + c + 1]       = __logf(acc[mf][nf][1]) - lc1;
            Op[(size_t)(r0 + 8) * NSUM + c]     = __logf(acc[mf][nf][2]) - lc0;
            Op[(size_t)(r0 + 8) * NSUM + c + 1] = __logf(acc[mf][nf][3]) - lc1;
        }
    }
}

extern "C" void kernel_launch(void* const* d_in, const int* in_sizes, int n_in,
                              void* d_out, int out_size)
{
    const float* x    = (const float*)d_in[0];
    const float* accs = (const float*)d_in[1];
    if (n_in >= 2 && in_sizes[0] > in_sizes[1]) {   // defensive order check
        const float* tmp = x; x = accs; accs = tmp;
    }
    // pass 1: exp(X) -> bf16 scratch   (16.8M elems / 8 per thread / 256)
    expx_kernel<<<(NSD * BDIM * NIN) / (8 * 256), 256>>>(x);
    // pass 2: GEMM + log epilogue
    dim3 grid(NSUM / NT, NSD);   // (8, 256)
    densesum_kernel<<<grid, 256>>>(accs, (float*)d_out);
}

// round 7
// speedup vs baseline: 1.1549x; 1.1549x over previous
#include <cuda_runtime.h>
#include <cuda_bf16.h>
#include <cstdint>

// out[b,k] = log( sum_n exp(x[b,n]) * exp(acc[n,k]) ) - log( sum_n exp(acc[n,k]) )
// per (s,d): GEMM M=128, N=512, K=512.
// Pass 1: exp(X) -> bf16 scratch.
// Pass 2: HMMA GEMM. A: bf16 cp.async ring (4 stages). W: fp32 cp.async ring
// (4 stages) -> smem convert (exp->bf16) -> Bs double buffer. 3-chunk prefetch
// distance kills the long_scoreboard stalls seen in R6 (issue 24%, all pipes idle).

#define NSD     256
#define BDIM    128
#define NIN     512
#define NSUM    512
#define KC      32
#define NT      64
#define APITCH  40          // bf16/row (80B): LDSM conflict-free (verified R3/R6)
#define BPITCH  72          // bf16/row (144B): LDSM conflict-free
#define NCH     (NIN/KC)    // 16
#define RING    4
#define ASTG    (BDIM*APITCH*2)     // 10240 B per A stage
#define WSTG    (KC*NT*4)           // 8192 B per W stage (fp32)
#define BSBUF   (KC*BPITCH*2)       // 4608 B per Bs buffer
#define SM_A    0
#define SM_W    (RING*ASTG)                 // 40960
#define SM_B    (SM_W + RING*WSTG)          // 73728
#define SM_TOT  (SM_B + 2*BSBUF)            // 82944

__device__ __nv_bfloat16 g_xe[(size_t)NSD * BDIM * NIN];   // 33.5MB scratch

__device__ __forceinline__ unsigned packbf(float a, float b) {
    __nv_bfloat162 h = __floats2bfloat162_rn(a, b);
    return *reinterpret_cast<unsigned const*>(&h);
}
__device__ __forceinline__ uint32_t s2u(const void* p) {
    uint32_t a;
    asm("{ .reg .u64 t; cvta.to.shared.u64 t, %1; cvt.u32.u64 %0, t; }" : "=r"(a) : "l"(p));
    return a;
}

// ---------------- Pass 1: Xe = bf16(exp(X)) ----------------
__global__ __launch_bounds__(256) void expx_kernel(const float* __restrict__ X) {
    const size_t i = ((size_t)blockIdx.x * blockDim.x + threadIdx.x) * 8;
    float4 a = *reinterpret_cast<const float4*>(X + i);
    float4 b = *reinterpret_cast<const float4*>(X + i + 4);
    uint4 u;
    u.x = packbf(__expf(a.x), __expf(a.y));
    u.y = packbf(__expf(a.z), __expf(a.w));
    u.z = packbf(__expf(b.x), __expf(b.y));
    u.w = packbf(__expf(b.z), __expf(b.w));
    *reinterpret_cast<uint4*>(g_xe + i) = u;
}

// ---------------- Pass 2: GEMM + log epilogue ----------------
__global__ __launch_bounds__(256, 2) void densesum_kernel(
    const float* __restrict__ W,   // [NSD][NIN][NSUM]
    float* __restrict__ O)         // [NSD][BDIM][NSUM]
{
    extern __shared__ __align__(16) char smem[];
    __shared__ float csums[NT];

    const int ct = blockIdx.x;     // 0..7
    const int sd = blockIdx.y;     // 0..255

    const __nv_bfloat16* Xe = g_xe + (size_t)sd * BDIM * NIN;
    const float* Wp = W + (size_t)sd * NIN * NSUM + ct * NT;
    float*       Op = O + (size_t)sd * BDIM * NSUM + ct * NT;

    const int t = threadIdx.x;
    if (t < NT) csums[t] = 0.f;

    const int warp = t >> 5, lane = t & 31;
    const int wm = warp >> 1, wn = warp & 1;
    const int l15 = lane & 15, lhi = lane >> 4;

    const uint32_t smb = s2u(smem);
    // A cp.async mapping: cid = t, t+256; row = cid>>2, 16B unit = cid&3
    const int arow0 = t >> 2,         ac40 = t & 3;
    const int arow1 = (t + 256) >> 2, ac41 = (t + 256) & 3;
    // W cp.async mapping: cid = t, t+256; row r = cid>>4 (k), 16B unit = cid&15
    const int wrow0 = t >> 4,         wc0 = t & 15;
    const int wrow1 = (t + 256) >> 4, wc1 = (t + 256) & 15;
    // convert / Bs mapping (same as R3): br = t>>4, bc = (t&15)*4, rows br+16j
    const int br = t >> 4, bc = (t & 15) * 4;

    // ldmatrix per-lane offsets (within a stage/buffer)
    const uint32_t aln = (uint32_t)((wm * 32 + l15) * APITCH + lhi * 8) * 2;
    const uint32_t bln = (uint32_t)(l15 * BPITCH + wn * 32 + lhi * 8) * 2;

    float acc[2][4][4];
    #pragma unroll
    for (int i = 0; i < 2; i++)
        #pragma unroll
        for (int j = 0; j < 4; j++)
            #pragma unroll
            for (int k = 0; k < 4; k++) acc[i][j][k] = 0.f;
    float csum[4] = {0.f, 0.f, 0.f, 0.f};

    // ---- issue one stage (A bf16 + W fp32) ----
    auto issue_stage = [&](int st) {
        const uint32_t aslot = smb + SM_A + (uint32_t)((st & (RING - 1)) * ASTG);
        const uint32_t wslot = smb + SM_W + (uint32_t)((st & (RING - 1)) * WSTG);
        const __nv_bfloat16* Xs = Xe + st * KC;
        const float*         Ws = Wp + (size_t)st * KC * NSUM;
        asm volatile("cp.async.cg.shared.global [%0], [%1], 16;"
                     :: "r"(aslot + (uint32_t)(arow0 * 80 + ac40 * 16)),
                        "l"(Xs + (size_t)arow0 * NIN + ac40 * 8));
        asm volatile("cp.async.cg.shared.global [%0], [%1], 16;"
                     :: "r"(aslot + (uint32_t)(arow1 * 80 + ac41 * 16)),
                        "l"(Xs + (size_t)arow1 * NIN + ac41 * 8));
        asm volatile("cp.async.cg.shared.global [%0], [%1], 16;"
                     :: "r"(wslot + (uint32_t)(wrow0 * 256 + wc0 * 16)),
                        "l"(Ws + (size_t)wrow0 * NSUM + wc0 * 4));
        asm volatile("cp.async.cg.shared.global [%0], [%1], 16;"
                     :: "r"(wslot + (uint32_t)(wrow1 * 256 + wc1 * 16)),
                        "l"(Ws + (size_t)wrow1 * NSUM + wc1 * 4));
    };

    // prologue: stages 0..2 in flight
    #pragma unroll
    for (int s = 0; s < RING - 1; s++) {
        issue_stage(s);
        asm volatile("cp.async.commit_group;" ::: "memory");
    }

    for (int ch = 0; ch < NCH; ch++) {
        const int buf = ch & 1;
        const uint32_t aslot = smb + SM_A + (uint32_t)((ch & (RING - 1)) * ASTG);
        const uint32_t wslot = smb + SM_W + (uint32_t)((ch & (RING - 1)) * WSTG);
        const uint32_t bbuf  = smb + SM_B + (uint32_t)(buf * BSBUF);

        // s1+s2: stage ch resident for all threads
        asm volatile("cp.async.wait_group %0;" :: "n"(RING - 2) : "memory");
        __syncthreads();

        // s3: convert W(ch): LDS fp32 -> exp -> bf16 STS + csums
        #pragma unroll
        for (int j = 0; j < 2; j++) {
            float4 v;
            asm volatile("ld.shared.v4.f32 {%0,%1,%2,%3}, [%4];"
                         : "=f"(v.x), "=f"(v.y), "=f"(v.z), "=f"(v.w)
                         : "r"(wslot + (uint32_t)(j * 4096 + t * 16)));
            float e0 = __expf(v.x), e1 = __expf(v.y), e2 = __expf(v.z), e3 = __expf(v.w);
            csum[0] += e0; csum[1] += e1; csum[2] += e2; csum[3] += e3;
            asm volatile("st.shared.v2.b32 [%0], {%1,%2};"
                         :: "r"(bbuf + (uint32_t)(((br + 16 * j) * BPITCH + bc) * 2)),
                            "r"(packbf(e0, e1)), "r"(packbf(e2, e3)) : "memory");
        }
        // s4: Bs[buf] ready
        __syncthreads();

        // s5: issue stage ch+3 (empty commit otherwise — keeps wait_group accounting exact)
        if (ch + RING - 1 < NCH) issue_stage(ch + RING - 1);
        asm volatile("cp.async.commit_group;" ::: "memory");

        // s6: MMA(ch): fragments via ldmatrix from A ring slot + Bs[buf]
        #pragma unroll
        for (int ks = 0; ks < 2; ks++) {
            unsigned afr[2][4];
            #pragma unroll
            for (int mf = 0; mf < 2; mf++) {
                const uint32_t addr = aslot + aln
                    + (uint32_t)(mf * 16 * APITCH * 2) + (uint32_t)(ks * 32);
                asm volatile(
                    "ldmatrix.sync.aligned.m8n8.x4.shared.b16 {%0,%1,%2,%3}, [%4];"
                    : "=r"(afr[mf][0]), "=r"(afr[mf][1]),
                      "=r"(afr[mf][2]), "=r"(afr[mf][3]) : "r"(addr));
            }
            unsigned bfr[2][4];
            #pragma unroll
            for (int np = 0; np < 2; np++) {
                const uint32_t addr = bbuf + bln
                    + (uint32_t)(ks * 16 * BPITCH * 2) + (uint32_t)(np * 32);
                asm volatile(
                    "ldmatrix.sync.aligned.m8n8.x4.trans.shared.b16 {%0,%1,%2,%3}, [%4];"
                    : "=r"(bfr[np][0]), "=r"(bfr[np][1]),
                      "=r"(bfr[np][2]), "=r"(bfr[np][3]) : "r"(addr));
            }
            #pragma unroll
            for (int mf = 0; mf < 2; mf++)
                #pragma unroll
                for (int nf = 0; nf < 4; nf++) {
                    const int np = nf >> 1, sel = (nf & 1) * 2;
                    asm volatile(
                        "mma.sync.aligned.m16n8k16.row.col.f32.bf16.bf16.f32 "
                        "{%0,%1,%2,%3}, {%4,%5,%6,%7}, {%8,%9}, {%0,%1,%2,%3};\n"
                        : "+f"(acc[mf][nf][0]), "+f"(acc[mf][nf][1]),
                          "+f"(acc[mf][nf][2]), "+f"(acc[mf][nf][3])
                        : "r"(afr[mf][0]), "r"(afr[mf][1]),
                          "r"(afr[mf][2]), "r"(afr[mf][3]),
                          "r"(bfr[np][sel]), "r"(bfr[np][sel + 1]));
                }
        }
    }

    // column-sum reduce
    atomicAdd(&csums[bc + 0], csum[0]);
    atomicAdd(&csums[bc + 1], csum[1]);
    atomicAdd(&csums[bc + 2], csum[2]);
    atomicAdd(&csums[bc + 3], csum[3]);
    __syncthreads();

    // epilogue: out = log(P) - log(C[col])
    const int g = lane >> 2, q = lane & 3;
    #pragma unroll
    for (int nf = 0; nf < 4; nf++) {
        const int c = wn * 32 + nf * 8 + q * 2;
        const float lc0 = __logf(csums[c]);
        const float lc1 = __logf(csums[c + 1]);
        #pragma unroll
        for (int mf = 0; mf < 2; mf++) {
            const int r0 = wm * 32 + mf * 16 + g;
            Op[(size_t)r0 * NSUM + c]           = __logf(acc[mf][nf][0]) - lc0;
            Op[(size_t)r0 * NSUM + c + 1]       = __logf(acc[mf][nf][1]) - lc1;
            Op[(size_t)(r0 + 8) * NSUM + c]     = __logf(acc[mf][nf][2]) - lc0;
            Op[(size_t)(r0 + 8) * NSUM + c + 1] = __logf(acc[mf][nf][3]) - lc1;
        }
    }
}

extern "C" void kernel_launch(void* const* d_in, const int* in_sizes, int n_in,
                              void* d_out, int out_size)
{
    const float* x    = (const float*)d_in[0];
    const float* accs = (const float*)d_in[1];
    if (n_in >= 2 && in_sizes[0] > in_sizes[1]) {
        const float* tmp = x; x = accs; accs = tmp;
    }
    cudaFuncSetAttribute(densesum_kernel,
                         cudaFuncAttributeMaxDynamicSharedMemorySize, SM_TOT);
    expx_kernel<<<(NSD * BDIM * NIN) / (8 * 256), 256>>>(x);
    dim3 grid(NSUM / NT, NSD);   // (8, 256)
    densesum_kernel<<<grid, 256, SM_TOT>>>(accs, (float*)d_out);
}

// round 9
// speedup vs baseline: 1.2159x; 1.0528x over previous
#include <cuda_runtime.h>
#include <cuda_bf16.h>
#include <cstdint>

// out[b,k] = log( sum_n exp(x[b,n]) * exp(acc[n,k]) ) - log( sum_n exp(acc[n,k]) )
// per (s,d): GEMM M=128, N=512, K=512.
// Pass 1: exp(X) -> bf16 scratch.
// Pass 2: HMMA GEMM, 4-stage cp.async ring for A(bf16)+W(fp32).
// R8: ONE barrier per chunk; convert(ch+1) overlaps MMA(ch).

#define NSD     256
#define BDIM    128
#define NIN     512
#define NSUM    512
#define KC      32
#define NT      64
#define APITCH  40          // bf16/row (80B): LDSM conflict-free
#define BPITCH  72          // bf16/row (144B): LDSM conflict-free
#define NCH     (NIN/KC)    // 16
#define RING    4
#define ASTG    (BDIM*APITCH*2)     // 10240 B
#define WSTG    (KC*NT*4)           // 8192 B
#define BSBUF   (KC*BPITCH*2)       // 4608 B
#define SM_A    0
#define SM_W    (RING*ASTG)
#define SM_B    (SM_W + RING*WSTG)
#define SM_TOT  (SM_B + 2*BSBUF)    // 82944

__device__ __nv_bfloat16 g_xe[(size_t)NSD * BDIM * NIN];   // 33.5MB scratch

__device__ __forceinline__ unsigned packbf(float a, float b) {
    __nv_bfloat162 h = __floats2bfloat162_rn(a, b);
    return *reinterpret_cast<unsigned const*>(&h);
}
__device__ __forceinline__ uint32_t s2u(const void* p) {
    uint32_t a;
    asm("{ .reg .u64 t; cvta.to.shared.u64 t, %1; cvt.u32.u64 %0, t; }" : "=r"(a) : "l"(p));
    return a;
}

// ---------------- Pass 1: Xe = bf16(exp(X)) ----------------
__global__ __launch_bounds__(256) void expx_kernel(const float* __restrict__ X) {
    const size_t i = ((size_t)blockIdx.x * blockDim.x + threadIdx.x) * 8;
    float4 a = *reinterpret_cast<const float4*>(X + i);
    float4 b = *reinterpret_cast<const float4*>(X + i + 4);
    uint4 u;
    u.x = packbf(__expf(a.x), __expf(a.y));
    u.y = packbf(__expf(a.z), __expf(a.w));
    u.z = packbf(__expf(b.x), __expf(b.y));
    u.w = packbf(__expf(b.z), __expf(b.w));
    *reinterpret_cast<uint4*>(g_xe + i) = u;
}

// ---------------- Pass 2: GEMM + log epilogue ----------------
__global__ __launch_bounds__(256, 2) void densesum_kernel(
    const float* __restrict__ W,   // [NSD][NIN][NSUM]
    float* __restrict__ O)         // [NSD][BDIM][NSUM]
{
    extern __shared__ __align__(16) char smem[];
    __shared__ float csums[NT];

    const int ct = blockIdx.x;     // 0..7
    const int sd = blockIdx.y;     // 0..255

    const __nv_bfloat16* Xe = g_xe + (size_t)sd * BDIM * NIN;
    const float* Wp = W + (size_t)sd * NIN * NSUM + ct * NT;
    float*       Op = O + (size_t)sd * BDIM * NSUM + ct * NT;

    const int t = threadIdx.x;
    if (t < NT) csums[t] = 0.f;

    const int warp = t >> 5, lane = t & 31;
    const int wm = warp >> 1, wn = warp & 1;
    const int l15 = lane & 15, lhi = lane >> 4;

    const uint32_t smb = s2u(smem);
    const int arow0 = t >> 2,         ac40 = t & 3;
    const int arow1 = (t + 256) >> 2, ac41 = (t + 256) & 3;
    const int wrow0 = t >> 4,         wc0 = t & 15;
    const int wrow1 = (t + 256) >> 4, wc1 = (t + 256) & 15;
    const int br = t >> 4, bc = (t & 15) * 4;

    const uint32_t aln = (uint32_t)((wm * 32 + l15) * APITCH + lhi * 8) * 2;
    const uint32_t bln = (uint32_t)(l15 * BPITCH + wn * 32 + lhi * 8) * 2;

    float acc[2][4][4];
    #pragma unroll
    for (int i = 0; i < 2; i++)
        #pragma unroll
        for (int j = 0; j < 4; j++)
            #pragma unroll
            for (int k = 0; k < 4; k++) acc[i][j][k] = 0.f;
    float csum[4] = {0.f, 0.f, 0.f, 0.f};

    auto issue_stage = [&](int st) {
        const uint32_t aslot = smb + SM_A + (uint32_t)((st & (RING - 1)) * ASTG);
        const uint32_t wslot = smb + SM_W + (uint32_t)((st & (RING - 1)) * WSTG);
        const __nv_bfloat16* Xs = Xe + st * KC;
        const float*         Ws = Wp + (size_t)st * KC * NSUM;
        asm volatile("cp.async.cg.shared.global [%0], [%1], 16;"
                     :: "r"(aslot + (uint32_t)(arow0 * 80 + ac40 * 16)),
                        "l"(Xs + (size_t)arow0 * NIN + ac40 * 8));
        asm volatile("cp.async.cg.shared.global [%0], [%1], 16;"
                     :: "r"(aslot + (uint32_t)(arow1 * 80 + ac41 * 16)),
                        "l"(Xs + (size_t)arow1 * NIN + ac41 * 8));
        asm volatile("cp.async.cg.shared.global [%0], [%1], 16;"
                     :: "r"(wslot + (uint32_t)(wrow0 * 256 + wc0 * 16)),
                        "l"(Ws + (size_t)wrow0 * NSUM + wc0 * 4));
        asm volatile("cp.async.cg.shared.global [%0], [%1], 16;"
                     :: "r"(wslot + (uint32_t)(wrow1 * 256 + wc1 * 16)),
                        "l"(Ws + (size_t)wrow1 * NSUM + wc1 * 4));
    };

    // convert chunk st: W ring slot -> exp -> Bs[st&1] + csum
    auto convert = [&](int st) {
        const uint32_t wslot = smb + SM_W + (uint32_t)((st & (RING - 1)) * WSTG);
        const uint32_t bbuf  = smb + SM_B + (uint32_t)((st & 1) * BSBUF);
        #pragma unroll
        for (int j = 0; j < 2; j++) {
            float4 v;
            asm volatile("ld.shared.v4.f32 {%0,%1,%2,%3}, [%4];"
                         : "=f"(v.x), "=f"(v.y), "=f"(v.z), "=f"(v.w)
                         : "r"(wslot + (uint32_t)(j * 4096 + t * 16)));
            float e0 = __expf(v.x), e1 = __expf(v.y), e2 = __expf(v.z), e3 = __expf(v.w);
            csum[0] += e0; csum[1] += e1; csum[2] += e2; csum[3] += e3;
            asm volatile("st.shared.v2.b32 [%0], {%1,%2};"
                         :: "r"(bbuf + (uint32_t)(((br + 16 * j) * BPITCH + bc) * 2)),
                            "r"(packbf(e0, e1)), "r"(packbf(e2, e3)) : "memory");
        }
    };

    // prologue: stages 0..2 in flight; convert(0)
    #pragma unroll
    for (int s = 0; s < RING - 1; s++) {
        issue_stage(s);
        asm volatile("cp.async.commit_group;" ::: "memory");
    }
    asm volatile("cp.async.wait_group %0;" :: "n"(RING - 2) : "memory");
    __syncthreads();
    convert(0);

    for (int ch = 0; ch < NCH; ch++) {
        const uint32_t aslot = smb + SM_A + (uint32_t)((ch & (RING - 1)) * ASTG);
        const uint32_t bbuf  = smb + SM_B + (uint32_t)((ch & 1) * BSBUF);

        // one barrier: Bs[ch&1] ready; all readers of ring slot (ch-1)%4 and of
        // Bs[(ch+1)&1] have drained.
        __syncthreads();

        // early A-frag loads for MMA(ch) (independent of the convert stream)
        unsigned afr[2][2][4];   // [ks][mf][4]
        #pragma unroll
        for (int ks = 0; ks < 2; ks++)
            #pragma unroll
            for (int mf = 0; mf < 2; mf++) {
                const uint32_t addr = aslot + aln
                    + (uint32_t)(mf * 16 * APITCH * 2) + (uint32_t)(ks * 32);
                asm volatile(
                    "ldmatrix.sync.aligned.m8n8.x4.shared.b16 {%0,%1,%2,%3}, [%4];"
                    : "=r"(afr[ks][mf][0]), "=r"(afr[ks][mf][1]),
                      "=r"(afr[ks][mf][2]), "=r"(afr[ks][mf][3]) : "r"(addr));
            }

        // issue stage ch+3 into slot (ch-1)%4; always commit (exact accounting)
        if (ch + RING - 1 < NCH) issue_stage(ch + RING - 1);
        asm volatile("cp.async.commit_group;" ::: "memory");

        // convert NEXT chunk — overlaps with this chunk's MMA stream below
        if (ch + 1 < NCH) {
            asm volatile("cp.async.wait_group %0;" :: "n"(RING - 2) : "memory");
            convert(ch + 1);
        }

        // MMA(ch): B-frags from Bs[ch&1] + HMMA
        #pragma unroll
        for (int ks = 0; ks < 2; ks++) {
            unsigned bfr[2][4];
            #pragma unroll
            for (int np = 0; np < 2; np++) {
                const uint32_t addr = bbuf + bln
                    + (uint32_t)(ks * 16 * BPITCH * 2) + (uint32_t)(np * 32);
                asm volatile(
                    "ldmatrix.sync.aligned.m8n8.x4.trans.shared.b16 {%0,%1,%2,%3}, [%4];"
                    : "=r"(bfr[np][0]), "=r"(bfr[np][1]),
                      "=r"(bfr[np][2]), "=r"(bfr[np][3]) : "r"(addr));
            }
            #pragma unroll
            for (int mf = 0; mf < 2; mf++)
                #pragma unroll
                for (int nf = 0; nf < 4; nf++) {
                    const int np = nf >> 1, sel = (nf & 1) * 2;
                    asm volatile(
                        "mma.sync.aligned.m16n8k16.row.col.f32.bf16.bf16.f32 "
                        "{%0,%1,%2,%3}, {%4,%5,%6,%7}, {%8,%9}, {%0,%1,%2,%3};\n"
                        : "+f"(acc[mf][nf][0]), "+f"(acc[mf][nf][1]),
                          "+f"(acc[mf][nf][2]), "+f"(acc[mf][nf][3])
                        : "r"(afr[ks][mf][0]), "r"(afr[ks][mf][1]),
                          "r"(afr[ks][mf][2]), "r"(afr[ks][mf][3]),
                          "r"(bfr[np][sel]), "r"(bfr[np][sel + 1]));
                }
        }
    }

    // column-sum reduce
    atomicAdd(&csums[bc + 0], csum[0]);
    atomicAdd(&csums[bc + 1], csum[1]);
    atomicAdd(&csums[bc + 2], csum[2]);
    atomicAdd(&csums[bc + 3], csum[3]);
    __syncthreads();

    // epilogue: out = log(P) - log(C[col])
    const int g = lane >> 2, q = lane & 3;
    #pragma unroll
    for (int nf = 0; nf < 4; nf++) {
        const int c = wn * 32 + nf * 8 + q * 2;
        const float lc0 = __logf(csums[c]);
        const float lc1 = __logf(csums[c + 1]);
        #pragma unroll
        for (int mf = 0; mf < 2; mf++) {
            const int r0 = wm * 32 + mf * 16 + g;
            Op[(size_t)r0 * NSUM + c]           = __logf(acc[mf][nf][0]) - lc0;
            Op[(size_t)r0 * NSUM + c + 1]       = __logf(acc[mf][nf][1]) - lc1;
            Op[(size_t)(r0 + 8) * NSUM + c]     = __logf(acc[mf][nf][2]) - lc0;
            Op[(size_t)(r0 + 8) * NSUM + c + 1] = __logf(acc[mf][nf][3]) - lc1;
        }
    }
}

extern "C" void kernel_launch(void* const* d_in, const int* in_sizes, int n_in,
                              void* d_out, int out_size)
{
    const float* x    = (const float*)d_in[0];
    const float* accs = (const float*)d_in[1];
    if (n_in >= 2 && in_sizes[0] > in_sizes[1]) {
        const float* tmp = x; x = accs; accs = tmp;
    }
    cudaFuncSetAttribute(densesum_kernel,
                         cudaFuncAttributeMaxDynamicSharedMemorySize, SM_TOT);
    expx_kernel<<<(NSD * BDIM * NIN) / (8 * 256), 256>>>(x);
    dim3 grid(NSUM / NT, NSD);   // (8, 256)
    densesum_kernel<<<grid, 256, SM_TOT>>>(accs, (float*)d_out);
}

// round 10
// speedup vs baseline: 1.3133x; 1.0801x over previous
#include <cuda_runtime.h>
#include <cuda_bf16.h>
#include <cstdint>

// out[b,k] = log( sum_n exp(x[b,n]) * exp(acc[n,k]) ) - log( sum_n exp(acc[n,k]) )
// per (s,d): GEMM M=128, N=512, K=512.
// Pass 1: exp(X) -> bf16 scratch.
// Pass 2: HMMA GEMM, 3-stage cp.async ring for A(bf16)+W(fp32), one barrier per
// chunk, convert(ch+1) overlapped with MMA(ch).
// R10: RING 4->3 + launch_bounds(256,3) => 3 CTAs/SM (occ 24%->36%).

#define NSD     256
#define BDIM    128
#define NIN     512
#define NSUM    512
#define KC      32
#define NT      64
#define APITCH  40          // bf16/row (80B): LDSM conflict-free
#define BPITCH  72          // bf16/row (144B): LDSM conflict-free
#define NCH     (NIN/KC)    // 16
#define RING    3
#define ASTG    (BDIM*APITCH*2)     // 10240 B
#define WSTG    (KC*NT*4)           // 8192 B
#define BSBUF   (KC*BPITCH*2)       // 4608 B
#define SM_A    0
#define SM_W    (RING*ASTG)                 // 30720
#define SM_B    (SM_W + RING*WSTG)          // 55296
#define SM_TOT  (SM_B + 2*BSBUF)            // 64512

__device__ __nv_bfloat16 g_xe[(size_t)NSD * BDIM * NIN];   // 33.5MB scratch

__device__ __forceinline__ unsigned packbf(float a, float b) {
    __nv_bfloat162 h = __floats2bfloat162_rn(a, b);
    return *reinterpret_cast<unsigned const*>(&h);
}
__device__ __forceinline__ uint32_t s2u(const void* p) {
    uint32_t a;
    asm("{ .reg .u64 t; cvta.to.shared.u64 t, %1; cvt.u32.u64 %0, t; }" : "=r"(a) : "l"(p));
    return a;
}

// ---------------- Pass 1: Xe = bf16(exp(X)) ----------------
__global__ __launch_bounds__(256) void expx_kernel(const float* __restrict__ X) {
    const size_t i = ((size_t)blockIdx.x * blockDim.x + threadIdx.x) * 8;
    float4 a = *reinterpret_cast<const float4*>(X + i);
    float4 b = *reinterpret_cast<const float4*>(X + i + 4);
    uint4 u;
    u.x = packbf(__expf(a.x), __expf(a.y));
    u.y = packbf(__expf(a.z), __expf(a.w));
    u.z = packbf(__expf(b.x), __expf(b.y));
    u.w = packbf(__expf(b.z), __expf(b.w));
    *reinterpret_cast<uint4*>(g_xe + i) = u;
}

// ---------------- Pass 2: GEMM + log epilogue ----------------
__global__ __launch_bounds__(256, 3) void densesum_kernel(
    const float* __restrict__ W,   // [NSD][NIN][NSUM]
    float* __restrict__ O)         // [NSD][BDIM][NSUM]
{
    extern __shared__ __align__(16) char smem[];
    __shared__ float csums[NT];

    const int ct = blockIdx.x;     // 0..7
    const int sd = blockIdx.y;     // 0..255

    const __nv_bfloat16* Xe = g_xe + (size_t)sd * BDIM * NIN;
    const float* Wp = W + (size_t)sd * NIN * NSUM + ct * NT;
    float*       Op = O + (size_t)sd * BDIM * NSUM + ct * NT;

    const int t = threadIdx.x;
    if (t < NT) csums[t] = 0.f;

    const int warp = t >> 5, lane = t & 31;
    const int wm = warp >> 1, wn = warp & 1;
    const int l15 = lane & 15, lhi = lane >> 4;

    const uint32_t smb = s2u(smem);
    const int arow0 = t >> 2,         ac40 = t & 3;
    const int arow1 = (t + 256) >> 2, ac41 = (t + 256) & 3;
    const int wrow0 = t >> 4,         wc0 = t & 15;
    const int wrow1 = (t + 256) >> 4, wc1 = (t + 256) & 15;
    const int br = t >> 4, bc = (t & 15) * 4;

    const uint32_t aln = (uint32_t)((wm * 32 + l15) * APITCH + lhi * 8) * 2;
    const uint32_t bln = (uint32_t)(l15 * BPITCH + wn * 32 + lhi * 8) * 2;

    float acc[2][4][4];
    #pragma unroll
    for (int i = 0; i < 2; i++)
        #pragma unroll
        for (int j = 0; j < 4; j++)
            #pragma unroll
            for (int k = 0; k < 4; k++) acc[i][j][k] = 0.f;
    float csum[4] = {0.f, 0.f, 0.f, 0.f};

    auto issue_stage = [&](int st) {
        const uint32_t aslot = smb + SM_A + (uint32_t)((st % RING) * ASTG);
        const uint32_t wslot = smb + SM_W + (uint32_t)((st % RING) * WSTG);
        const __nv_bfloat16* Xs = Xe + st * KC;
        const float*         Ws = Wp + (size_t)st * KC * NSUM;
        asm volatile("cp.async.cg.shared.global [%0], [%1], 16;"
                     :: "r"(aslot + (uint32_t)(arow0 * 80 + ac40 * 16)),
                        "l"(Xs + (size_t)arow0 * NIN + ac40 * 8));
        asm volatile("cp.async.cg.shared.global [%0], [%1], 16;"
                     :: "r"(aslot + (uint32_t)(arow1 * 80 + ac41 * 16)),
                        "l"(Xs + (size_t)arow1 * NIN + ac41 * 8));
        asm volatile("cp.async.cg.shared.global [%0], [%1], 16;"
                     :: "r"(wslot + (uint32_t)(wrow0 * 256 + wc0 * 16)),
                        "l"(Ws + (size_t)wrow0 * NSUM + wc0 * 4));
        asm volatile("cp.async.cg.shared.global [%0], [%1], 16;"
                     :: "r"(wslot + (uint32_t)(wrow1 * 256 + wc1 * 16)),
                        "l"(Ws + (size_t)wrow1 * NSUM + wc1 * 4));
    };

    // convert chunk st: W ring slot -> exp -> Bs[st&1] + csum.
    // Reads exactly this thread's own cp.async chunks (t*16, 4096+t*16).
    auto convert = [&](int st) {
        const uint32_t wslot = smb + SM_W + (uint32_t)((st % RING) * WSTG);
        const uint32_t bbuf  = smb + SM_B + (uint32_t)((st & 1) * BSBUF);
        #pragma unroll
        for (int j = 0; j < 2; j++) {
            float4 v;
            asm volatile("ld.shared.v4.f32 {%0,%1,%2,%3}, [%4];"
                         : "=f"(v.x), "=f"(v.y), "=f"(v.z), "=f"(v.w)
                         : "r"(wslot + (uint32_t)(j * 4096 + t * 16)));
            float e0 = __expf(v.x), e1 = __expf(v.y), e2 = __expf(v.z), e3 = __expf(v.w);
            csum[0] += e0; csum[1] += e1; csum[2] += e2; csum[3] += e3;
            asm volatile("st.shared.v2.b32 [%0], {%1,%2};"
                         :: "r"(bbuf + (uint32_t)(((br + 16 * j) * BPITCH + bc) * 2)),
                            "r"(packbf(e0, e1)), "r"(packbf(e2, e3)) : "memory");
        }
    };

    // prologue: stages 0,1 in flight; convert(0)
    #pragma unroll
    for (int s = 0; s < RING - 1; s++) {
        issue_stage(s);
        asm volatile("cp.async.commit_group;" ::: "memory");
    }
    asm volatile("cp.async.wait_group %0;" :: "n"(RING - 2) : "memory");
    convert(0);

    for (int ch = 0; ch < NCH; ch++) {
        const uint32_t aslot = smb + SM_A + (uint32_t)((ch % RING) * ASTG);
        const uint32_t bbuf  = smb + SM_B + (uint32_t)((ch & 1) * BSBUF);

        // one barrier: Bs[ch&1] visible to all warps; readers of ring slot
        // (ch-1)%3 and of Bs[(ch+1)&1] drained.
        __syncthreads();

        // issue stage ch+2 into slot (ch-1)%3; always commit (exact accounting)
        if (ch + RING - 1 < NCH) issue_stage(ch + RING - 1);
        asm volatile("cp.async.commit_group;" ::: "memory");

        // convert NEXT chunk — overlaps with this chunk's MMA stream below
        if (ch + 1 < NCH) {
            asm volatile("cp.async.wait_group %0;" :: "n"(RING - 2) : "memory");
            convert(ch + 1);
        }

        // MMA(ch): fragments via ldmatrix from A ring slot + Bs[ch&1]
        #pragma unroll
        for (int ks = 0; ks < 2; ks++) {
            unsigned afr[2][4];
            #pragma unroll
            for (int mf = 0; mf < 2; mf++) {
                const uint32_t addr = aslot + aln
                    + (uint32_t)(mf * 16 * APITCH * 2) + (uint32_t)(ks * 32);
                asm volatile(
                    "ldmatrix.sync.aligned.m8n8.x4.shared.b16 {%0,%1,%2,%3}, [%4];"
                    : "=r"(afr[mf][0]), "=r"(afr[mf][1]),
                      "=r"(afr[mf][2]), "=r"(afr[mf][3]) : "r"(addr));
            }
            unsigned bfr[2][4];
            #pragma unroll
            for (int np = 0; np < 2; np++) {
                const uint32_t addr = bbuf + bln
                    + (uint32_t)(ks * 16 * BPITCH * 2) + (uint32_t)(np * 32);
                asm volatile(
                    "ldmatrix.sync.aligned.m8n8.x4.trans.shared.b16 {%0,%1,%2,%3}, [%4];"
                    : "=r"(bfr[np][0]), "=r"(bfr[np][1]),
                      "=r"(bfr[np][2]), "=r"(bfr[np][3]) : "r"(addr));
            }
            #pragma unroll
            for (int mf = 0; mf < 2; mf++)
                #pragma unroll
                for (int nf = 0; nf < 4; nf++) {
                    const int np = nf >> 1, sel = (nf & 1) * 2;
                    asm volatile(
                        "mma.sync.aligned.m16n8k16.row.col.f32.bf16.bf16.f32 "
                        "{%0,%1,%2,%3}, {%4,%5,%6,%7}, {%8,%9}, {%0,%1,%2,%3};\n"
                        : "+f"(acc[mf][nf][0]), "+f"(acc[mf][nf][1]),
                          "+f"(acc[mf][nf][2]), "+f"(acc[mf][nf][3])
                        : "r"(afr[mf][0]), "r"(afr[mf][1]),
                          "r"(afr[mf][2]), "r"(afr[mf][3]),
                          "r"(bfr[np][sel]), "r"(bfr[np][sel + 1]));
                }
        }
    }

    // column-sum reduce
    atomicAdd(&csums[bc + 0], csum[0]);
    atomicAdd(&csums[bc + 1], csum[1]);
    atomicAdd(&csums[bc + 2], csum[2]);
    atomicAdd(&csums[bc + 3], csum[3]);
    __syncthreads();

    // epilogue: out = log(P) - log(C[col])
    const int g = lane >> 2, q = lane & 3;
    #pragma unroll
    for (int nf = 0; nf < 4; nf++) {
        const int c = wn * 32 + nf * 8 + q * 2;
        const float lc0 = __logf(csums[c]);
        const float lc1 = __logf(csums[c + 1]);
        #pragma unroll
        for (int mf = 0; mf < 2; mf++) {
            const int r0 = wm * 32 + mf * 16 + g;
            Op[(size_t)r0 * NSUM + c]           = __logf(acc[mf][nf][0]) - lc0;
            Op[(size_t)r0 * NSUM + c + 1]       = __logf(acc[mf][nf][1]) - lc1;
            Op[(size_t)(r0 + 8) * NSUM + c]     = __logf(acc[mf][nf][2]) - lc0;
            Op[(size_t)(r0 + 8) * NSUM + c + 1] = __logf(acc[mf][nf][3]) - lc1;
        }
    }
}

extern "C" void kernel_launch(void* const* d_in, const int* in_sizes, int n_in,
                              void* d_out, int out_size)
{
    const float* x    = (const float*)d_in[0];
    const float* accs = (const float*)d_in[1];
    if (n_in >= 2 && in_sizes[0] > in_sizes[1]) {
        const float* tmp = x; x = accs; accs = tmp;
    }
    cudaFuncSetAttribute(densesum_kernel,
                         cudaFuncAttributeMaxDynamicSharedMemorySize, SM_TOT);
    expx_kernel<<<(NSD * BDIM * NIN) / (8 * 256), 256>>>(x);
    dim3 grid(NSUM / NT, NSD);   // (8, 256)
    densesum_kernel<<<grid, 256, SM_TOT>>>(accs, (float*)d_out);
}

// round 13
// speedup vs baseline: 1.3229x; 1.0073x over previous
#include <cuda_runtime.h>
#include <cuda_bf16.h>
#include <cstdint>

// out[b,k] = log( sum_n exp(x[b,n]) * exp(acc[n,k]) ) - log( sum_n exp(acc[n,k]) )
// per (s,d): GEMM M=128, N=512, K=512.
// Pass 1: exp(X) -> bf16 scratch.
// Pass 2: HMMA GEMM. A: 3-stage bf16 ring, W: 2-stage fp32 ring, both issued at
// distance 2 and retired ONE ITERATION BEFORE the consuming barrier (fixes the
// R11 cross-thread cp.async visibility race). One barrier/chunk; convert(ch+1)
// overlaps MMA(ch). 4 CTAs/SM (smem 56.3KB, 64 regs).

#define NSD     256
#define BDIM    128
#define NIN     512
#define NSUM    512
#define KC      32
#define NT      64
#define APITCH  40          // bf16/row (80B): LDSM conflict-free
#define BPITCH  72          // bf16/row (144B): LDSM conflict-free
#define NCH     (NIN/KC)    // 16
#define RINGA   3
#define RINGW   2
#define ASTG    (BDIM*APITCH*2)     // 10240 B
#define WSTG    (KC*NT*4)           // 8192 B
#define BSBUF   (KC*BPITCH*2)       // 4608 B
#define SM_A    0
#define SM_W    (RINGA*ASTG)                // 30720
#define SM_B    (SM_W + RINGW*WSTG)         // 47104
#define SM_TOT  (SM_B + 2*BSBUF)            // 56320

__device__ __nv_bfloat16 g_xe[(size_t)NSD * BDIM * NIN];   // 33.5MB scratch

__device__ __forceinline__ unsigned packbf(float a, float b) {
    __nv_bfloat162 h = __floats2bfloat162_rn(a, b);
    return *reinterpret_cast<unsigned const*>(&h);
}
__device__ __forceinline__ uint32_t s2u(const void* p) {
    uint32_t a;
    asm("{ .reg .u64 t; cvta.to.shared.u64 t, %1; cvt.u32.u64 %0, t; }" : "=r"(a) : "l"(p));
    return a;
}

// ---------------- Pass 1: Xe = bf16(exp(X)) ----------------
__global__ __launch_bounds__(256) void expx_kernel(const float* __restrict__ X) {
    const size_t i = ((size_t)blockIdx.x * blockDim.x + threadIdx.x) * 8;
    float4 a = *reinterpret_cast<const float4*>(X + i);
    float4 b = *reinterpret_cast<const float4*>(X + i + 4);
    uint4 u;
    u.x = packbf(__expf(a.x), __expf(a.y));
    u.y = packbf(__expf(a.z), __expf(a.w));
    u.z = packbf(__expf(b.x), __expf(b.y));
    u.w = packbf(__expf(b.z), __expf(b.w));
    *reinterpret_cast<uint4*>(g_xe + i) = u;
}

// ---------------- Pass 2: GEMM + log epilogue ----------------
__global__ __launch_bounds__(256, 4) void densesum_kernel(
    const float* __restrict__ W,   // [NSD][NIN][NSUM]
    float* __restrict__ O)         // [NSD][BDIM][NSUM]
{
    extern __shared__ __align__(16) char smem[];
    __shared__ float csums[NT];

    const int ct = blockIdx.x;     // 0..7
    const int sd = blockIdx.y;     // 0..255

    const __nv_bfloat16* Xe = g_xe + (size_t)sd * BDIM * NIN;
    const float* Wp = W + (size_t)sd * NIN * NSUM + ct * NT;
    float*       Op = O + (size_t)sd * BDIM * NSUM + ct * NT;

    const int t = threadIdx.x;
    if (t < NT) csums[t] = 0.f;

    const int warp = t >> 5, lane = t & 31;
    const int wm = warp >> 1, wn = warp & 1;
    const int l15 = lane & 15, lhi = lane >> 4;

    const uint32_t smb = s2u(smem);
    const int arow0 = t >> 2,         ac40 = t & 3;
    const int arow1 = (t + 256) >> 2, ac41 = (t + 256) & 3;
    const int wrow0 = t >> 4,         wc0 = t & 15;
    const int wrow1 = (t + 256) >> 4, wc1 = (t + 256) & 15;
    const int br = t >> 4, bc = (t & 15) * 4;

    const uint32_t aln = (uint32_t)((wm * 32 + l15) * APITCH + lhi * 8) * 2;
    const uint32_t bln = (uint32_t)(l15 * BPITCH + wn * 32 + lhi * 8) * 2;

    float acc[2][4][4];
    #pragma unroll
    for (int i = 0; i < 2; i++)
        #pragma unroll
        for (int j = 0; j < 4; j++)
            #pragma unroll
            for (int k = 0; k < 4; k++) acc[i][j][k] = 0.f;
    float csum[4] = {0.f, 0.f, 0.f, 0.f};

    auto issue_a = [&](int st) {
        const uint32_t aslot = smb + SM_A + (uint32_t)((st % RINGA) * ASTG);
        const __nv_bfloat16* Xs = Xe + st * KC;
        asm volatile("cp.async.cg.shared.global [%0], [%1], 16;"
                     :: "r"(aslot + (uint32_t)(arow0 * 80 + ac40 * 16)),
                        "l"(Xs + (size_t)arow0 * NIN + ac40 * 8));
        asm volatile("cp.async.cg.shared.global [%0], [%1], 16;"
                     :: "r"(aslot + (uint32_t)(arow1 * 80 + ac41 * 16)),
                        "l"(Xs + (size_t)arow1 * NIN + ac41 * 8));
    };
    auto issue_w = [&](int st) {
        const uint32_t wslot = smb + SM_W + (uint32_t)((st % RINGW) * WSTG);
        const float* Ws = Wp + (size_t)st * KC * NSUM;
        asm volatile("cp.async.cg.shared.global [%0], [%1], 16;"
                     :: "r"(wslot + (uint32_t)(wrow0 * 256 + wc0 * 16)),
                        "l"(Ws + (size_t)wrow0 * NSUM + wc0 * 4));
        asm volatile("cp.async.cg.shared.global [%0], [%1], 16;"
                     :: "r"(wslot + (uint32_t)(wrow1 * 256 + wc1 * 16)),
                        "l"(Ws + (size_t)wrow1 * NSUM + wc1 * 4));
    };

    // convert chunk st: W ring slot -> exp -> Bs[st&1] + csum.
    // Reads ONLY this thread's own cp.async chunks (t*16, 4096+t*16), so the
    // thread's own wait_group suffices for visibility (no barrier needed).
    auto convert = [&](int st) {
        const uint32_t wslot = smb + SM_W + (uint32_t)((st % RINGW) * WSTG);
        const uint32_t bbuf  = smb + SM_B + (uint32_t)((st & 1) * BSBUF);
        #pragma unroll
        for (int j = 0; j < 2; j++) {
            float4 v;
            asm volatile("ld.shared.v4.f32 {%0,%1,%2,%3}, [%4];"
                         : "=f"(v.x), "=f"(v.y), "=f"(v.z), "=f"(v.w)
                         : "r"(wslot + (uint32_t)(j * 4096 + t * 16)));
            float e0 = __expf(v.x), e1 = __expf(v.y), e2 = __expf(v.z), e3 = __expf(v.w);
            csum[0] += e0; csum[1] += e1; csum[2] += e2; csum[3] += e3;
            asm volatile("st.shared.v2.b32 [%0], {%1,%2};"
                         :: "r"(bbuf + (uint32_t)(((br + 16 * j) * BPITCH + bc) * 2)),
                            "r"(packbf(e0, e1)), "r"(packbf(e2, e3)) : "memory");
        }
    };

    // prologue: {A0}{W0}{A1}{W1}; wait_group 2 retires {A0},{W0}; convert(0).
    issue_a(0);
    asm volatile("cp.async.commit_group;" ::: "memory");
    issue_w(0);
    asm volatile("cp.async.commit_group;" ::: "memory");
    issue_a(1);
    asm volatile("cp.async.commit_group;" ::: "memory");
    issue_w(1);
    asm volatile("cp.async.commit_group;" ::: "memory");
    asm volatile("cp.async.wait_group 2;" ::: "memory");
    convert(0);

    for (int ch = 0; ch < NCH; ch++) {
        const uint32_t aslot = smb + SM_A + (uint32_t)((ch % RINGA) * ASTG);
        const uint32_t bbuf  = smb + SM_B + (uint32_t)((ch & 1) * BSBUF);

        // one barrier: publishes A(ch) (group retired by ALL threads at iter
        // ch-1's wait) and Bs[ch&1] (written by convert(ch) in iter ch-1).
        __syncthreads();

        // issue distance-2 stages; always commit (exact ledger: 2 groups/iter)
        if (ch + 2 < NCH) issue_a(ch + 2);   // slot (ch+2)%3; reader MMA(ch-1) pre-barrier
        asm volatile("cp.async.commit_group;" ::: "memory");
        if (ch + 2 < NCH) issue_w(ch + 2);   // slot ch%2; prior reader convert(ch), same thread
        asm volatile("cp.async.commit_group;" ::: "memory");

        // retire {A(ch+1)},{W(ch+1)}; keep the two just-issued groups pending
        asm volatile("cp.async.wait_group 2;" ::: "memory");

        // convert NEXT chunk — overlaps this chunk's MMA stream below
        if (ch + 1 < NCH) convert(ch + 1);

        // MMA(ch): fragments via ldmatrix from A slot ch%3 + Bs[ch&1]
        #pragma unroll
        for (int ks = 0; ks < 2; ks++) {
            unsigned afr[2][4];
            #pragma unroll
            for (int mf = 0; mf < 2; mf++) {
                const uint32_t addr = aslot + aln
                    + (uint32_t)(mf * 16 * APITCH * 2) + (uint32_t)(ks * 32);
                asm volatile(
                    "ldmatrix.sync.aligned.m8n8.x4.shared.b16 {%0,%1,%2,%3}, [%4];"
                    : "=r"(afr[mf][0]), "=r"(afr[mf][1]),
                      "=r"(afr[mf][2]), "=r"(afr[mf][3]) : "r"(addr));
            }
            unsigned bfr[2][4];
            #pragma unroll
            for (int np = 0; np < 2; np++) {
                const uint32_t addr = bbuf + bln
                    + (uint32_t)(ks * 16 * BPITCH * 2) + (uint32_t)(np * 32);
                asm volatile(
                    "ldmatrix.sync.aligned.m8n8.x4.trans.shared.b16 {%0,%1,%2,%3}, [%4];"
                    : "=r"(bfr[np][0]), "=r"(bfr[np][1]),
                      "=r"(bfr[np][2]), "=r"(bfr[np][3]) : "r"(addr));
            }
            #pragma unroll
            for (int mf = 0; mf < 2; mf++)
                #pragma unroll
                for (int nf = 0; nf < 4; nf++) {
                    const int np = nf >> 1, sel = (nf & 1) * 2;
                    asm volatile(
                        "mma.sync.aligned.m16n8k16.row.col.f32.bf16.bf16.f32 "
                        "{%0,%1,%2,%3}, {%4,%5,%6,%7}, {%8,%9}, {%0,%1,%2,%3};\n"
                        : "+f"(acc[mf][nf][0]), "+f"(acc[mf][nf][1]),
                          "+f"(acc[mf][nf][2]), "+f"(acc[mf][nf][3])
                        : "r"(afr[mf][0]), "r"(afr[mf][1]),
                          "r"(afr[mf][2]), "r"(afr[mf][3]),
                          "r"(bfr[np][sel]), "r"(bfr[np][sel + 1]));
                }
        }
    }

    // column-sum reduce
    atomicAdd(&csums[bc + 0], csum[0]);
    atomicAdd(&csums[bc + 1], csum[1]);
    atomicAdd(&csums[bc + 2], csum[2]);
    atomicAdd(&csums[bc + 3], csum[3]);
    __syncthreads();

    // epilogue: out = log(P) - log(C[col])
    const int g = lane >> 2, q = lane & 3;
    #pragma unroll
    for (int nf = 0; nf < 4; nf++) {
        const int c = wn * 32 + nf * 8 + q * 2;
        const float lc0 = __logf(csums[c]);
        const float lc1 = __logf(csums[c + 1]);
        #pragma unroll
        for (int mf = 0; mf < 2; mf++) {
            const int r0 = wm * 32 + mf * 16 + g;
            Op[(size_t)r0 * NSUM + c]           = __logf(acc[mf][nf][0]) - lc0;
            Op[(size_t)r0 * NSUM + c + 1]       = __logf(acc[mf][nf][1]) - lc1;
            Op[(size_t)(r0 + 8) * NSUM + c]     = __logf(acc[mf][nf][2]) - lc0;
            Op[(size_t)(r0 + 8) * NSUM + c + 1] = __logf(acc[mf][nf][3]) - lc1;
        }
    }
}

extern "C" void kernel_launch(void* const* d_in, const int* in_sizes, int n_in,
                              void* d_out, int out_size)
{
    const float* x    = (const float*)d_in[0];
    const float* accs = (const float*)d_in[1];
    if (n_in >= 2 && in_sizes[0] > in_sizes[1]) {
        const float* tmp = x; x = accs; accs = tmp;
    }
    cudaFuncSetAttribute(densesum_kernel,
                         cudaFuncAttributeMaxDynamicSharedMemorySize, SM_TOT);
    expx_kernel<<<(NSD * BDIM * NIN) / (8 * 256), 256>>>(x);
    dim3 grid(NSUM / NT, NSD);   // (8, 256)
    densesum_kernel<<<grid, 256, SM_TOT>>>(accs, (float*)d_out);
}

// round 15
// speedup vs baseline: 1.4647x; 1.1072x over previous
#include <cuda_runtime.h>
#include <cuda_bf16.h>
#include <cstdint>

// out[b,k] = log( sum_n exp(x[b,n]) * exp(acc[n,k]) ) - log( sum_n exp(acc[n,k]) )
// per (s,d): GEMM M=128, N=512, K=512.
// Pass 1: exp(X) -> bf16 scratch.
// Pass 2: HMMA GEMM. A: 3-stage bf16 ring, W: 2-stage fp32 ring, distance-2
// issue, retire one iter before the consuming barrier. One barrier/chunk;
// convert(ch+1) overlaps MMA(ch). 4 CTAs/SM.
// R14: manual slot rotation (no % in loop), unroll 2, STG.64 epilogue.

#define NSD     256
#define BDIM    128
#define NIN     512
#define NSUM    512
#define KC      32
#define NT      64
#define APITCH  40          // bf16/row (80B): LDSM conflict-free
#define BPITCH  72          // bf16/row (144B): LDSM conflict-free
#define NCH     (NIN/KC)    // 16
#define RINGA   3
#define RINGW   2
#define ASTG    (BDIM*APITCH*2)     // 10240 B
#define WSTG    (KC*NT*4)           // 8192 B
#define BSBUF   (KC*BPITCH*2)       // 4608 B
#define SM_A    0
#define SM_W    (RINGA*ASTG)                // 30720
#define SM_B    (SM_W + RINGW*WSTG)         // 47104
#define SM_TOT  (SM_B + 2*BSBUF)            // 56320

__device__ __nv_bfloat16 g_xe[(size_t)NSD * BDIM * NIN];   // 33.5MB scratch

__device__ __forceinline__ unsigned packbf(float a, float b) {
    __nv_bfloat162 h = __floats2bfloat162_rn(a, b);
    return *reinterpret_cast<unsigned const*>(&h);
}
__device__ __forceinline__ uint32_t s2u(const void* p) {
    uint32_t a;
    asm("{ .reg .u64 t; cvta.to.shared.u64 t, %1; cvt.u32.u64 %0, t; }" : "=r"(a) : "l"(p));
    return a;
}

// ---------------- Pass 1: Xe = bf16(exp(X)) ----------------
__global__ __launch_bounds__(256) void expx_kernel(const float* __restrict__ X) {
    const size_t i = ((size_t)blockIdx.x * blockDim.x + threadIdx.x) * 8;
    float4 a = *reinterpret_cast<const float4*>(X + i);
    float4 b = *reinterpret_cast<const float4*>(X + i + 4);
    uint4 u;
    u.x = packbf(__expf(a.x), __expf(a.y));
    u.y = packbf(__expf(a.z), __expf(a.w));
    u.z = packbf(__expf(b.x), __expf(b.y));
    u.w = packbf(__expf(b.z), __expf(b.w));
    *reinterpret_cast<uint4*>(g_xe + i) = u;
}

// ---------------- Pass 2: GEMM + log epilogue ----------------
__global__ __launch_bounds__(256, 4) void densesum_kernel(
    const float* __restrict__ W,   // [NSD][NIN][NSUM]
    float* __restrict__ O)         // [NSD][BDIM][NSUM]
{
    extern __shared__ __align__(16) char smem[];
    __shared__ float csums[NT];

    const int ct = blockIdx.x;     // 0..7
    const int sd = blockIdx.y;     // 0..255

    const __nv_bfloat16* Xe = g_xe + (size_t)sd * BDIM * NIN;
    const float* Wp = W + (size_t)sd * NIN * NSUM + ct * NT;
    float*       Op = O + (size_t)sd * BDIM * NSUM + ct * NT;

    const int t = threadIdx.x;
    if (t < NT) csums[t] = 0.f;

    const int warp = t >> 5, lane = t & 31;
    const int wm = warp >> 1, wn = warp & 1;
    const int l15 = lane & 15, lhi = lane >> 4;

    const uint32_t smb = s2u(smem);
    const int arow0 = t >> 2,         ac40 = t & 3;
    const int arow1 = (t + 256) >> 2, ac41 = (t + 256) & 3;
    const int wrow0 = t >> 4,         wc0 = t & 15;
    const int wrow1 = (t + 256) >> 4, wc1 = (t + 256) & 15;
    const int br = t >> 4, bc = (t & 15) * 4;

    const uint32_t aln = (uint32_t)((wm * 32 + l15) * APITCH + lhi * 8) * 2;
    const uint32_t bln = (uint32_t)(l15 * BPITCH + wn * 32 + lhi * 8) * 2;

    // precomputed slot base addresses (manual rotation; no % in the loop)
    const uint32_t aA0 = smb + SM_A, aA1 = aA0 + ASTG, aA2 = aA1 + ASTG;
    const uint32_t wA0 = smb + SM_W, wA1 = wA0 + WSTG;
    const uint32_t bA0 = smb + SM_B, bA1 = bA0 + BSBUF;

    float acc[2][4][4];
    #pragma unroll
    for (int i = 0; i < 2; i++)
        #pragma unroll
        for (int j = 0; j < 4; j++)
            #pragma unroll
            for (int k = 0; k < 4; k++) acc[i][j][k] = 0.f;
    float csum[4] = {0.f, 0.f, 0.f, 0.f};

    auto issue_a = [&](uint32_t aslot, int st) {
        const __nv_bfloat16* Xs = Xe + st * KC;
        asm volatile("cp.async.cg.shared.global [%0], [%1], 16;"
                     :: "r"(aslot + (uint32_t)(arow0 * 80 + ac40 * 16)),
                        "l"(Xs + (size_t)arow0 * NIN + ac40 * 8));
        asm volatile("cp.async.cg.shared.global [%0], [%1], 16;"
                     :: "r"(aslot + (uint32_t)(arow1 * 80 + ac41 * 16)),
                        "l"(Xs + (size_t)arow1 * NIN + ac41 * 8));
    };
    auto issue_w = [&](uint32_t wslot, int st) {
        const float* Ws = Wp + (size_t)st * KC * NSUM;
        asm volatile("cp.async.cg.shared.global [%0], [%1], 16;"
                     :: "r"(wslot + (uint32_t)(wrow0 * 256 + wc0 * 16)),
                        "l"(Ws + (size_t)wrow0 * NSUM + wc0 * 4));
        asm volatile("cp.async.cg.shared.global [%0], [%1], 16;"
                     :: "r"(wslot + (uint32_t)(wrow1 * 256 + wc1 * 16)),
                        "l"(Ws + (size_t)wrow1 * NSUM + wc1 * 4));
    };

    // convert: W slot -> exp -> Bs buf + csum. Reads ONLY this thread's own
    // cp.async chunks (t*16, 4096+t*16) => own wait_group suffices.
    auto convert = [&](uint32_t wslot, uint32_t bbuf) {
        #pragma unroll
        for (int j = 0; j < 2; j++) {
            float4 v;
            asm volatile("ld.shared.v4.f32 {%0,%1,%2,%3}, [%4];"
                         : "=f"(v.x), "=f"(v.y), "=f"(v.z), "=f"(v.w)
                         : "r"(wslot + (uint32_t)(j * 4096 + t * 16)));
            float e0 = __expf(v.x), e1 = __expf(v.y), e2 = __expf(v.z), e3 = __expf(v.w);
            csum[0] += e0; csum[1] += e1; csum[2] += e2; csum[3] += e3;
            asm volatile("st.shared.v2.b32 [%0], {%1,%2};"
                         :: "r"(bbuf + (uint32_t)(((br + 16 * j) * BPITCH + bc) * 2)),
                            "r"(packbf(e0, e1)), "r"(packbf(e2, e3)) : "memory");
        }
    };

    // prologue: {A0}{W0}{A1}{W1}; wait_group 2 retires {A0},{W0}; convert(0).
    issue_a(aA0, 0);
    asm volatile("cp.async.commit_group;" ::: "memory");
    issue_w(wA0, 0);
    asm volatile("cp.async.commit_group;" ::: "memory");
    issue_a(aA1, 1);
    asm volatile("cp.async.commit_group;" ::: "memory");
    issue_w(wA1, 1);
    asm volatile("cp.async.commit_group;" ::: "memory");
    asm volatile("cp.async.wait_group 2;" ::: "memory");
    convert(wA0, bA0);

    // rotating slot registers: asl0 = slot(ch%3); wcur/bcur = slot(ch%2)
    uint32_t asl0 = aA0, asl1 = aA1, asl2 = aA2;
    uint32_t wcur = wA0, wnxt = wA1;
    uint32_t bcur = bA0, bnxt = bA1;

    #pragma unroll 2
    for (int ch = 0; ch < NCH; ch++) {
        // one barrier: publishes A(ch) (retired by all threads at iter ch-1's
        // wait) and Bs cur (written by convert(ch) in iter ch-1).
        __syncthreads();

        // distance-2 issues; always commit (exact ledger: 2 groups/iter)
        if (ch + 2 < NCH) issue_a(asl2, ch + 2);   // slot (ch+2)%3; reader MMA(ch-1) pre-barrier
        asm volatile("cp.async.commit_group;" ::: "memory");
        if (ch + 2 < NCH) issue_w(wcur, ch + 2);   // slot ch%2; prior reader convert(ch), same thread
        asm volatile("cp.async.commit_group;" ::: "memory");

        // retire {A(ch+1)},{W(ch+1)}; keep the two just-issued groups pending
        asm volatile("cp.async.wait_group 2;" ::: "memory");

        // convert NEXT chunk — overlaps this chunk's MMA stream below
        if (ch + 1 < NCH) convert(wnxt, bnxt);

        // MMA(ch): fragments via ldmatrix from asl0 + bcur
        #pragma unroll
        for (int ks = 0; ks < 2; ks++) {
            unsigned afr[2][4];
            #pragma unroll
            for (int mf = 0; mf < 2; mf++) {
                const uint32_t addr = asl0 + aln
                    + (uint32_t)(mf * 16 * APITCH * 2) + (uint32_t)(ks * 32);
                asm volatile(
                    "ldmatrix.sync.aligned.m8n8.x4.shared.b16 {%0,%1,%2,%3}, [%4];"
                    : "=r"(afr[mf][0]), "=r"(afr[mf][1]),
                      "=r"(afr[mf][2]), "=r"(afr[mf][3]) : "r"(addr));
            }
            unsigned bfr[2][4];
            #pragma unroll
            for (int np = 0; np < 2; np++) {
                const uint32_t addr = bcur + bln
                    + (uint32_t)(ks * 16 * BPITCH * 2) + (uint32_t)(np * 32);
                asm volatile(
                    "ldmatrix.sync.aligned.m8n8.x4.trans.shared.b16 {%0,%1,%2,%3}, [%4];"
                    : "=r"(bfr[np][0]), "=r"(bfr[np][1]),
                      "=r"(bfr[np][2]), "=r"(bfr[np][3]) : "r"(addr));
            }
            #pragma unroll
            for (int mf = 0; mf < 2; mf++)
                #pragma unroll
                for (int nf = 0; nf < 4; nf++) {
                    const int np = nf >> 1, sel = (nf & 1) * 2;
                    asm volatile(
                        "mma.sync.aligned.m16n8k16.row.col.f32.bf16.bf16.f32 "
                        "{%0,%1,%2,%3}, {%4,%5,%6,%7}, {%8,%9}, {%0,%1,%2,%3};\n"
                        : "+f"(acc[mf][nf][0]), "+f"(acc[mf][nf][1]),
                          "+f"(acc[mf][nf][2]), "+f"(acc[mf][nf][3])
                        : "r"(afr[mf][0]), "r"(afr[mf][1]),
                          "r"(afr[mf][2]), "r"(afr[mf][3]),
                          "r"(bfr[np][sel]), "r"(bfr[np][sel + 1]));
                }
        }

        // rotate slots: A advances by one; W/Bs toggle
        uint32_t tmp = asl0; asl0 = asl1; asl1 = asl2; asl2 = tmp;
        uint32_t tw = wcur; wcur = wnxt; wnxt = tw;
        uint32_t tb = bcur; bcur = bnxt; bnxt = tb;
    }

    // column-sum reduce
    atomicAdd(&csums[bc + 0], csum[0]);
    atomicAdd(&csums[bc + 1], csum[1]);
    atomicAdd(&csums[bc + 2], csum[2]);
    atomicAdd(&csums[bc + 3], csum[3]);
    __syncthreads();
    if (t < NT) csums[t] = __logf(csums[t]);
    __syncthreads();

    // epilogue: out = log(P) - log(C[col]); vectorized STG.64
    const int g = lane >> 2, q = lane & 3;
    #pragma unroll
    for (int nf = 0; nf < 4; nf++) {
        const int c = wn * 32 + nf * 8 + q * 2;
        const float lc0 = csums[c];
        const float lc1 = csums[c + 1];
        #pragma unroll
        for (int mf = 0; mf < 2; mf++) {
            const int r0 = wm * 32 + mf * 16 + g;
            float2 v0, v1;
            v0.x = __logf(acc[mf][nf][0]) - lc0;
            v0.y = __logf(acc[mf][nf][1]) - lc1;
            v1.x = __logf(acc[mf][nf][2]) - lc0;
            v1.y = __logf(acc[mf][nf][3]) - lc1;
            *reinterpret_cast<float2*>(Op + (size_t)r0 * NSUM + c)       = v0;
            *reinterpret_cast<float2*>(Op + (size_t)(r0 + 8) * NSUM + c) = v1;
        }
    }
}

extern "C" void kernel_launch(void* const* d_in, const int* in_sizes, int n_in,
                              void* d_out, int out_size)
{
    const float* x    = (const float*)d_in[0];
    const float* accs = (const float*)d_in[1];
    if (n_in >= 2 && in_sizes[0] > in_sizes[1]) {
        const float* tmp = x; x = accs; accs = tmp;
    }
    cudaFuncSetAttribute(densesum_kernel,
                         cudaFuncAttributeMaxDynamicSharedMemorySize, SM_TOT);
    expx_kernel<<<(NSD * BDIM * NIN) / (8 * 256), 256>>>(x);
    dim3 grid(NSUM / NT, NSD);   // (8, 256)
    densesum_kernel<<<grid, 256, SM_TOT>>>(accs, (float*)d_out);
}